// round 8
// baseline (speedup 1.0000x reference)
#include <cuda_runtime.h>
#include <cstdint>

#define IMG  224
#define HW   (IMG * IMG)        // 50176
#define XWU  25                 // staged window width in x (16 + 4 + 4 + 1)
#define SW   25                 // smem row stride in ELEMENTS (odd)
#define YH   41                 // staged window rows in y (32 + 4 + 4 + 1)
#define PLANE (SW * YH)         // 1025 elements per plane
#define NT   512

// compile-time byte offsets inside one buffer's regions
#define PAIR_S (PLANE * 8)      // 8200 : image stride in pair region
#define PAIR_R (16 * SW * 8)    // 3200 : 16-row step in pair region
#define SCAL_S (PLANE * 4)      // 4100
#define SCAL_R (16 * SW * 4)    // 1600

__device__ __forceinline__ uint32_t s2u(const void* p) {
    uint32_t a;
    asm("{ .reg .u64 t; cvta.to.shared.u64 t, %1; cvt.u32.u64 %0, t; }"
        : "=r"(a) : "l"(p));
    return a;
}

template<int DOFF, int SOFF>
__device__ __forceinline__ void cpa(uint32_t db, const float* sb) {
    asm volatile("cp.async.ca.shared.global [%0+%2], [%1+%3], 4;"
                 :: "r"(db), "l"(sb), "n"(DOFF), "n"(SOFF));
}

// stage one (image S, row-step RR) site of one buffer
template<int S, int RR>
__device__ __forceinline__ void stage6(uint32_t pb, uint32_t sb_, const float* sp) {
    cpa<S * PAIR_S + RR * PAIR_R + 0, (0 * HW + RR * 16 * IMG) * 4>(pb, sp);
    cpa<S * PAIR_S + RR * PAIR_R + 4, (1 * HW + RR * 16 * IMG) * 4>(pb, sp);
    cpa<S * SCAL_S + RR * SCAL_R,     (2 * HW + RR * 16 * IMG) * 4>(sb_, sp);
}

// stage a full tile window into buffer (pb, sb_) from (b1, b2) at (sx0, sy0)
__device__ __forceinline__ void stage_tile(
    uint32_t pb, uint32_t sb_, const float* b1, const float* b2,
    int sx0, int sy0, int l, int w)
{
    if (l < XWU) {
        const int off0 = (sy0 + w) * IMG + sx0 + l;
        const float* s1p = b1 + off0;
        const float* s2p = b2 + off0;
        const uint32_t pbt = pb  + (uint32_t)((w * SW + l) * 8);
        const uint32_t sbt = sb_ + (uint32_t)((w * SW + l) * 4);
        stage6<0, 0>(pbt, sbt, s1p);
        stage6<0, 1>(pbt, sbt, s1p);
        stage6<1, 0>(pbt, sbt, s2p);
        stage6<1, 1>(pbt, sbt, s2p);
        if (w < YH - 32) {               // rows 32..40: warps 0..8
            stage6<0, 2>(pbt, sbt, s1p);
            stage6<1, 2>(pbt, sbt, s2p);
        }
    }
    asm volatile("cp.async.commit_group;");
}

__global__ __launch_bounds__(NT, 4) void vm_kernel(
    const float* __restrict__ im1, const float* __restrict__ im2,
    const float* __restrict__ C,   const float* __restrict__ M1,
    const float* __restrict__ M2,  float* __restrict__ out)
{
    __shared__ __align__(16) float2 pair[2][2 * PLANE];  // 2 x 16400 B
    __shared__ float               scal[2][2 * PLANE];   // 2 x  8200 B

    const int tid = threadIdx.x;
    const int l   = tid & 31;            // lane: y within tile
    const int w   = tid >> 5;            // warp: x within tile
    const int X0 = blockIdx.x * 32;      // two 16-wide subtiles
    const int Y0 = blockIdx.y * 32;
    const int n  = blockIdx.z;

    const float* b1 = im1 + n * 3 * HW;
    const float* b2 = im2 + n * 3 * HW;

    int sx0s[2], sy0;
    sx0s[0] = min(max(X0 - 4, 0), IMG - XWU);
    sx0s[1] = min(max(X0 + 16 - 4, 0), IMG - XWU);
    sy0     = min(max(Y0 - 4, 0), IMG - YH);

    // ── pipeline: stage both tiles (two commit groups) ──
    stage_tile(s2u(pair[0]), s2u(scal[0]), b1, b2, sx0s[0], sy0, l, w);
    stage_tile(s2u(pair[1]), s2u(scal[1]), b1, b2, sx0s[1], sy0, l, w);

    // ── C/M loads for both tiles (coalesced, overlap staging latency) ──
    const int y  = Y0 + l;
    const int i0 = (X0 + w) * IMG + y;
    const int i1 = i0 + 16 * IMG;
    float Cxs[2], Cys[2], m1s[2], m2s[2];
    Cxs[0] = __ldg(C  + (n * 2) * HW + i0);
    Cys[0] = __ldg(C  + (n * 2 + 1) * HW + i0);
    m1s[0] = __ldg(M1 + n * HW + i0);
    m2s[0] = __ldg(M2 + n * HW + i0);
    Cxs[1] = __ldg(C  + (n * 2) * HW + i1);
    Cys[1] = __ldg(C  + (n * 2 + 1) * HW + i1);
    m1s[1] = __ldg(M1 + n * HW + i1);
    m2s[1] = __ldg(M2 + n * HW + i1);

    const float fyv = (float)y;
    const float sy0f = (float)sy0;
    const float loy = sy0f, hiy = (float)(sy0 + YH - 1);
    float* outn = out + n * 3 * HW;

#pragma unroll
    for (int t = 0; t < 2; t++) {
        if (t == 0) asm volatile("cp.async.wait_group 1;");
        else        asm volatile("cp.async.wait_group 0;");
        __syncthreads();

        const int sx0 = sx0s[t];
        const float sx0f = (float)sx0;
        const float lox = sx0f, hix = (float)(sx0 + XWU - 1);
        const float fxv = (float)(X0 + 16 * t + w);
        const float Cx = Cxs[t], Cy = Cys[t];
        const float m1v = m1s[t], m2v = m2s[t];

        float res[3];
#pragma unroll
        for (int s = 0; s < 2; s++) {
            const float px = s ? (fxv - Cx) : (fxv + Cx);
            const float py = s ? (fyv - Cy) : (fyv + Cy);

            float fx = floorf(px), cx = ceilf(px);
            float fy = floorf(py), cy = ceilf(py);
            float wfx = 1.0f - (px - fx);
            float wcx = 1.0f - (cx - px);
            float wfy = 1.0f - (py - fy);
            float wcy = 1.0f - (cy - py);
            float wff = wfx * wfy, wcf = wcx * wfy;
            float wfc = wfx * wcy, wcc = wcx * wcy;

            float v0, v1, v2;
            if (fx >= lox && cx <= hix && fy >= loy && cy <= hiy) {
                // window ⊂ image → taps in-image → reference's flat-index
                // truncate/clip is a no-op; exact float-domain indices (<2^24)
                float dcf  = cx - fx;                    // 0 or 1
                float drf  = cy - fy;                    // 0 or 1
                float t00f = fmaf(fy - sy0f, (float)SW, fx - sx0f);
                float t10f = fmaf(drf, (float)SW, t00f);
                int t00 = (int)t00f;
                int t01 = (int)(t00f + dcf);
                int t10 = (int)t10f;
                int t11 = (int)(t10f + dcf);

                const float2* pp = pair[t] + s * PLANE;
                const float*  sp = scal[t] + s * PLANE;
                float2 a00 = pp[t00];
                float2 a01 = pp[t01];
                float2 a10 = pp[t10];
                float2 a11 = pp[t11];
                float  c00 = sp[t00];
                float  c01 = sp[t01];
                float  c10 = sp[t10];
                float  c11 = sp[t11];

                v0 = wff * a00.x;
                v0 = fmaf(wcf, a01.x, v0);
                v0 = fmaf(wfc, a10.x, v0);
                v0 = fmaf(wcc, a11.x, v0);
                v1 = wff * a00.y;
                v1 = fmaf(wcf, a01.y, v1);
                v1 = fmaf(wfc, a10.y, v1);
                v1 = fmaf(wcc, a11.y, v1);
                v2 = wff * c00;
                v2 = fmaf(wcf, c01, v2);
                v2 = fmaf(wfc, c10, v2);
                v2 = fmaf(wcc, c11, v2);
            } else {
                // exact reference fallback: ind = clip(int32(nx+224*ny),0,HW-1)
                const float* gim = s ? b2 : b1;
                int iff = (int)(fx + 224.0f * fy);
                int icf = (int)(cx + 224.0f * fy);
                int ifc = (int)(fx + 224.0f * cy);
                int icc = (int)(cx + 224.0f * cy);
                iff = min(max(iff, 0), HW - 1);
                icf = min(max(icf, 0), HW - 1);
                ifc = min(max(ifc, 0), HW - 1);
                icc = min(max(icc, 0), HW - 1);
                float acc[3];
#pragma unroll
                for (int ch = 0; ch < 3; ch++) {
                    const float* p = gim + ch * HW;
                    float v = wff * __ldg(p + iff);
                    v = fmaf(wcf, __ldg(p + icf), v);
                    v = fmaf(wfc, __ldg(p + ifc), v);
                    v = fmaf(wcc, __ldg(p + icc), v);
                    acc[ch] = v;
                }
                v0 = acc[0]; v1 = acc[1]; v2 = acc[2];
            }
            if (s == 0) { res[0] = v0 * m1v; res[1] = v1 * m1v; res[2] = v2 * m1v; }
            else        { res[0] = fmaf(v0, m2v, res[0]);
                          res[1] = fmaf(v1, m2v, res[1]);
                          res[2] = fmaf(v2, m2v, res[2]); }
        }

        const int i = (t == 0) ? i0 : i1;
#pragma unroll
        for (int ch = 0; ch < 3; ch++)
            outn[ch * HW + i] = res[ch];
    }
}

extern "C" void kernel_launch(void* const* d_in, const int* in_sizes, int n_in,
                              void* d_out, int out_size)
{
    const float* im1 = (const float*)d_in[0];
    const float* im2 = (const float*)d_in[1];
    const float* C   = (const float*)d_in[2];
    const float* M1  = (const float*)d_in[3];
    const float* M2  = (const float*)d_in[4];
    float* out = (float*)d_out;

    dim3 block(NT, 1, 1);
    dim3 grid(7, 7, 64);   // 3136 blocks, 2 tiles each
    vm_kernel<<<grid, block>>>(im1, im2, C, M1, M2, out);
}